// round 1
// baseline (speedup 1.0000x reference)
#include <cuda_runtime.h>
#include <cuda_bf16.h>
#include <cstdint>

#define N_ROWS 8192
#define DIM    512
#define BT     64            // 8192/128 tiles per dimension
#define MARGIN 0.35f

// ---------------- scratch (device globals; no allocation allowed) ----------
__device__ __align__(16) __nv_bfloat16 g_hi[N_ROWS * DIM];
__device__ __align__(16) __nv_bfloat16 g_lo[N_ROWS * DIM];
__device__ float    g_sq[N_ROWS];
__device__ float    g_ce[N_ROWS];
__device__ unsigned g_pos[N_ROWS];   // ordered-int encoded running max (same-label)
__device__ unsigned g_neg[N_ROWS];   // ordered-int encoded running min (diff-label)
__device__ int      g_lab[N_ROWS];
__device__ int      g_lab64;         // 1 if label buffer is int64, 0 if int32

// ---------------- float <-> monotone unsigned encoding ---------------------
__device__ __forceinline__ unsigned f2ord(float f) {
    unsigned u = __float_as_uint(f);
    return (u & 0x80000000u) ? ~u : (u | 0x80000000u);
}
__device__ __forceinline__ float ord2f(unsigned u) {
    unsigned b = (u & 0x80000000u) ? (u ^ 0x80000000u) : ~u;
    return __uint_as_float(b);
}

__device__ __forceinline__ float dev_inf() { return __int_as_float(0x7f800000); }

// ---------------- label width autodetect ------------------------------------
__global__ void detect_kernel(const int* raw) {
    __shared__ int bad;
    if (threadIdx.x == 0) bad = 0;
    __syncthreads();
    // If labels are int64 (values in [0,512)), every odd 32-bit word is 0.
    for (int i = threadIdx.x; i < 2048; i += blockDim.x)
        if (raw[2 * i + 1] != 0) bad = 1;
    __syncthreads();
    if (threadIdx.x == 0) g_lab64 = bad ? 0 : 1;
}

// ---------------- prep: norms, CE, bf16 hi/lo split, init reductions --------
__global__ void prep_kernel(const float* __restrict__ x, const void* __restrict__ labraw) {
    int row = blockIdx.x;
    int t   = threadIdx.x;          // 128 threads
    const float* xr = x + (size_t)row * DIM;

    float v[4];
#pragma unroll
    for (int i = 0; i < 4; i++) v[i] = xr[t + 128 * i];

    float ss = 0.f, mx = -dev_inf();
#pragma unroll
    for (int i = 0; i < 4; i++) { ss += v[i] * v[i]; mx = fmaxf(mx, v[i]); }
#pragma unroll
    for (int o = 16; o; o >>= 1) {
        ss += __shfl_xor_sync(0xffffffffu, ss, o);
        mx  = fmaxf(mx, __shfl_xor_sync(0xffffffffu, mx, o));
    }
    __shared__ float s_ss[4], s_mx[4], s_sq[4], s_se[4];
    int w = t >> 5, l = t & 31;
    if (l == 0) { s_ss[w] = ss; s_mx[w] = mx; }
    __syncthreads();
    ss = s_ss[0] + s_ss[1] + s_ss[2] + s_ss[3];
    mx = fmaxf(fmaxf(s_mx[0], s_mx[1]), fmaxf(s_mx[2], s_mx[3]));

    float norm = sqrtf(ss);
    float sq = 0.f, se = 0.f;
#pragma unroll
    for (int i = 0; i < 4; i++) {
        float xn = v[i] / norm;
        sq += xn * xn;
        se += expf(v[i] - mx);
    }
#pragma unroll
    for (int o = 16; o; o >>= 1) {
        sq += __shfl_xor_sync(0xffffffffu, sq, o);
        se += __shfl_xor_sync(0xffffffffu, se, o);
    }
    if (l == 0) { s_sq[w] = sq; s_se[w] = se; }
    __syncthreads();

    if (t == 0) {
        float sqt = s_sq[0] + s_sq[1] + s_sq[2] + s_sq[3];
        float set = s_se[0] + s_se[1] + s_se[2] + s_se[3];
        int lb = g_lab64 ? (int)((const long long*)labraw)[row]
                         : ((const int*)labraw)[row];
        g_sq[row]  = sqt;
        g_ce[row]  = mx + logf(set) - xr[lb];
        g_lab[row] = lb;
        g_pos[row] = f2ord(-dev_inf());
        g_neg[row] = f2ord(dev_inf());
    }

#pragma unroll
    for (int i = 0; i < 4; i++) {
        size_t idx = (size_t)row * DIM + t + 128 * i;
        __nv_bfloat16 h = __float2bfloat16(v[i]);
        g_hi[idx] = h;
        g_lo[idx] = __float2bfloat16(v[i] - __bfloat162float(h));
    }
}

// ---------------- mma helpers ----------------------------------------------
__device__ __forceinline__ void ldm_x4(uint32_t* d, uint32_t addr) {
    asm volatile("ldmatrix.sync.aligned.m8n8.x4.shared.b16 {%0,%1,%2,%3}, [%4];\n"
                 : "=r"(d[0]), "=r"(d[1]), "=r"(d[2]), "=r"(d[3]) : "r"(addr));
}
__device__ __forceinline__ void mma16816(float* c, const uint32_t* a, const uint32_t* b) {
    asm volatile(
        "mma.sync.aligned.m16n8k16.row.col.f32.bf16.bf16.f32 "
        "{%0,%1,%2,%3}, {%4,%5,%6,%7}, {%8,%9}, {%0,%1,%2,%3};\n"
        : "+f"(c[0]), "+f"(c[1]), "+f"(c[2]), "+f"(c[3])
        : "r"(a[0]), "r"(a[1]), "r"(a[2]), "r"(a[3]), "r"(b[0]), "r"(b[1]));
}

// swizzled 16B-chunk index for (row r, logical chunk c) inside a 128x32 bf16 tile
__device__ __forceinline__ int swz(int r, int c) { return r * 4 + (c ^ ((r >> 1) & 3)); }

// ---------------- fused triangular GEMM + masked max/min epilogue ----------
__global__ void __launch_bounds__(256) gemm_kernel() {
    // map linear block -> upper-triangular tile (bi <= bj)
    int b = blockIdx.x;
    int bi = 0;
    while ((bi + 1) * BT - ((bi + 1) * bi) / 2 <= b) bi++;
    int bj = bi + (b - (bi * BT - (bi * (bi - 1)) / 2));

    const int tid  = threadIdx.x;
    const int lane = tid & 31, warp = tid >> 5;
    const int wm = warp & 3, wn = warp >> 2;   // 4 x 2 warp grid: 32-row x 64-col per warp

    __shared__ __align__(16) __nv_bfloat16 sAh[128 * 32];
    __shared__ __align__(16) __nv_bfloat16 sAl[128 * 32];
    __shared__ __align__(16) __nv_bfloat16 sBh[128 * 32];
    __shared__ __align__(16) __nv_bfloat16 sBl[128 * 32];
    __shared__ float s_sqi[128], s_sqj[128];
    __shared__ int   s_li[128], s_lj[128];

    const int rowi0 = bi * 128, rowj0 = bj * 128;
    if (tid < 128) { s_sqi[tid] = g_sq[rowi0 + tid]; s_li[tid] = g_lab[rowi0 + tid]; }
    else { int t2 = tid - 128; s_sqj[t2] = g_sq[rowj0 + t2]; s_lj[t2] = g_lab[rowj0 + t2]; }

    float acc[2][8][4];
#pragma unroll
    for (int mi = 0; mi < 2; mi++)
#pragma unroll
        for (int ni = 0; ni < 8; ni++)
#pragma unroll
            for (int k = 0; k < 4; k++) acc[mi][ni][k] = 0.f;

    const uint32_t baseAh = (uint32_t)__cvta_generic_to_shared(sAh);
    const uint32_t baseAl = (uint32_t)__cvta_generic_to_shared(sAl);
    const uint32_t baseBh = (uint32_t)__cvta_generic_to_shared(sBh);
    const uint32_t baseBl = (uint32_t)__cvta_generic_to_shared(sBl);

    for (int kt = 0; kt < DIM; kt += 32) {
#pragma unroll
        for (int q0 = 0; q0 < 2; q0++) {
            int q = tid + q0 * 256;
            int r = q >> 2, c = q & 3;
            int p = swz(r, c);
            size_t goffA = (size_t)(rowi0 + r) * DIM + kt + c * 8;
            size_t goffB = (size_t)(rowj0 + r) * DIM + kt + c * 8;
            ((uint4*)sAh)[p] = *(const uint4*)(g_hi + goffA);
            ((uint4*)sAl)[p] = *(const uint4*)(g_lo + goffA);
            ((uint4*)sBh)[p] = *(const uint4*)(g_hi + goffB);
            ((uint4*)sBl)[p] = *(const uint4*)(g_lo + goffB);
        }
        __syncthreads();

#pragma unroll
        for (int kk = 0; kk < 2; kk++) {
            const int m4 = lane >> 3, ri = lane & 7;
            uint32_t ah[2][4], al[2][4];
#pragma unroll
            for (int mi = 0; mi < 2; mi++) {
                int r = wm * 32 + mi * 16 + (m4 & 1) * 8 + ri;
                int c = kk * 2 + (m4 >> 1);
                uint32_t off = (uint32_t)swz(r, c) << 4;
                ldm_x4(ah[mi], baseAh + off);
                ldm_x4(al[mi], baseAl + off);
            }
            uint32_t bh[4][4], bl[4][4];
#pragma unroll
            for (int p4 = 0; p4 < 4; p4++) {
                int r = wn * 64 + p4 * 16 + (m4 >> 1) * 8 + ri;
                int c = kk * 2 + (m4 & 1);
                uint32_t off = (uint32_t)swz(r, c) << 4;
                ldm_x4(bh[p4], baseBh + off);
                ldm_x4(bl[p4], baseBl + off);
            }
#pragma unroll
            for (int mi = 0; mi < 2; mi++)
#pragma unroll
                for (int ni = 0; ni < 8; ni++) {
                    const uint32_t* fh = &bh[ni >> 1][(ni & 1) * 2];
                    const uint32_t* fl = &bl[ni >> 1][(ni & 1) * 2];
                    mma16816(acc[mi][ni], ah[mi], fh);   // hi*hi
                    mma16816(acc[mi][ni], ah[mi], fl);   // hi*lo
                    mma16816(acc[mi][ni], al[mi], fh);   // lo*hi
                }
        }
        __syncthreads();
    }

    // ---------------- epilogue: dist + masked max/min reductions -----------
    const int g = lane >> 2, tg = lane & 3;
    const float NEG = -dev_inf(), POS = dev_inf();
    float rmax[2][2], rmin[2][2];
#pragma unroll
    for (int mi = 0; mi < 2; mi++)
#pragma unroll
        for (int h = 0; h < 2; h++) { rmax[mi][h] = NEG; rmin[mi][h] = POS; }
    float cmx[16], cmn[16];
#pragma unroll
    for (int s = 0; s < 16; s++) { cmx[s] = NEG; cmn[s] = POS; }

#pragma unroll
    for (int mi = 0; mi < 2; mi++)
#pragma unroll
        for (int h = 0; h < 2; h++) {
            int li = wm * 32 + mi * 16 + h * 8 + g;
            int labi = s_li[li];
            float sqi = s_sqi[li];
#pragma unroll
            for (int ni = 0; ni < 8; ni++)
#pragma unroll
                for (int cc = 0; cc < 2; cc++) {
                    int lj = wn * 64 + ni * 8 + tg * 2 + cc;
                    float d = sqi + s_sqj[lj] - 2.0f * acc[mi][ni][h * 2 + cc];
                    int s = ni * 2 + cc;
                    if (labi == s_lj[lj]) {
                        rmax[mi][h] = fmaxf(rmax[mi][h], d);
                        cmx[s] = fmaxf(cmx[s], d);
                    } else {
                        rmin[mi][h] = fminf(rmin[mi][h], d);
                        cmn[s] = fminf(cmn[s], d);
                    }
                }
        }

    // row reduction: lanes sharing g differ in tg (low 2 bits)
#pragma unroll
    for (int mi = 0; mi < 2; mi++)
#pragma unroll
        for (int h = 0; h < 2; h++) {
            float m_ = rmax[mi][h], n_ = rmin[mi][h];
            m_ = fmaxf(m_, __shfl_xor_sync(0xffffffffu, m_, 1));
            m_ = fmaxf(m_, __shfl_xor_sync(0xffffffffu, m_, 2));
            n_ = fminf(n_, __shfl_xor_sync(0xffffffffu, n_, 1));
            n_ = fminf(n_, __shfl_xor_sync(0xffffffffu, n_, 2));
            if (tg == 0) {
                int grow = rowi0 + wm * 32 + mi * 16 + h * 8 + g;
                atomicMax(&g_pos[grow], f2ord(m_));
                atomicMin(&g_neg[grow], f2ord(n_));
            }
        }

    // column reduction (symmetry): lanes sharing tg differ in g (bits 2..4)
    if (bi != bj) {
#pragma unroll
        for (int s = 0; s < 16; s++) {
            float m_ = cmx[s], n_ = cmn[s];
            m_ = fmaxf(m_, __shfl_xor_sync(0xffffffffu, m_, 4));
            m_ = fmaxf(m_, __shfl_xor_sync(0xffffffffu, m_, 8));
            m_ = fmaxf(m_, __shfl_xor_sync(0xffffffffu, m_, 16));
            n_ = fminf(n_, __shfl_xor_sync(0xffffffffu, n_, 4));
            n_ = fminf(n_, __shfl_xor_sync(0xffffffffu, n_, 8));
            n_ = fminf(n_, __shfl_xor_sync(0xffffffffu, n_, 16));
            if (g == 0) {
                int gcol = rowj0 + wn * 64 + (s >> 1) * 8 + tg * 2 + (s & 1);
                atomicMax(&g_pos[gcol], f2ord(m_));
                atomicMin(&g_neg[gcol], f2ord(n_));
            }
        }
    }
}

// ---------------- finalize: deterministic tree reduction --------------------
__global__ void finalize_kernel(float* out) {
    __shared__ float sh[256];
    int t = threadIdx.x;
    float ts = 0.f, cs = 0.f;
    for (int i = t; i < N_ROWS; i += 256) {
        float p = ord2f(g_pos[i]);
        float n = ord2f(g_neg[i]);
        ts += fmaxf(p - n + MARGIN, 0.0f);
        cs += g_ce[i];
    }
    sh[t] = ts; __syncthreads();
    for (int o = 128; o; o >>= 1) { if (t < o) sh[t] += sh[t + o]; __syncthreads(); }
    float tt = sh[0]; __syncthreads();
    sh[t] = cs; __syncthreads();
    for (int o = 128; o; o >>= 1) { if (t < o) sh[t] += sh[t + o]; __syncthreads(); }
    if (t == 0) out[0] = tt / (float)N_ROWS + sh[0] / (float)N_ROWS;
}

// ---------------- entry -----------------------------------------------------
extern "C" void kernel_launch(void* const* d_in, const int* in_sizes, int n_in,
                              void* d_out, int out_size) {
    const float* x   = (const float*)d_in[0];
    const void*  lab = d_in[1];

    detect_kernel<<<1, 256>>>((const int*)lab);
    prep_kernel<<<N_ROWS, 128>>>(x, lab);
    gemm_kernel<<<(BT * (BT + 1)) / 2, 256>>>();
    finalize_kernel<<<1, 256>>>((float*)d_out);
}

// round 3
// speedup vs baseline: 1.4608x; 1.4608x over previous
#include <cuda_runtime.h>
#include <cuda_bf16.h>
#include <cstdint>

#define N_ROWS 8192
#define DIM    512
#define BT     64            // 8192/128 tiles per dimension
#define MARGIN 0.35f
#define KC     32            // K elems per smem chunk
#define NCH    (DIM / KC)    // 16
#define STAGEB 32768         // 4 tiles x (128*32*2B)
#define SMEMDYN (2 * STAGEB) // double buffer

// ---------------- scratch (device globals; no allocation allowed) ----------
__device__ __align__(16) __nv_bfloat16 g_hi[N_ROWS * DIM];
__device__ __align__(16) __nv_bfloat16 g_lo[N_ROWS * DIM];
__device__ float    g_sq[N_ROWS];
__device__ float    g_ce[N_ROWS];
__device__ unsigned g_pos[N_ROWS];
__device__ unsigned g_neg[N_ROWS];
__device__ int      g_lab[N_ROWS];
__device__ int      g_lab64;

// ---------------- float <-> monotone unsigned encoding ---------------------
__device__ __forceinline__ unsigned f2ord(float f) {
    unsigned u = __float_as_uint(f);
    return (u & 0x80000000u) ? ~u : (u | 0x80000000u);
}
__device__ __forceinline__ float ord2f(unsigned u) {
    unsigned b = (u & 0x80000000u) ? (u ^ 0x80000000u) : ~u;
    return __uint_as_float(b);
}
__device__ __forceinline__ float dev_inf() { return __int_as_float(0x7f800000); }

// ---------------- label width autodetect ------------------------------------
__global__ void detect_kernel(const int* raw) {
    __shared__ int bad;
    if (threadIdx.x == 0) bad = 0;
    __syncthreads();
    for (int i = threadIdx.x; i < 2048; i += blockDim.x)
        if (raw[2 * i + 1] != 0) bad = 1;
    __syncthreads();
    if (threadIdx.x == 0) g_lab64 = bad ? 0 : 1;
}

// ---------------- prep: norms, CE, bf16 hi/lo split, init reductions --------
__global__ void prep_kernel(const float* __restrict__ x, const void* __restrict__ labraw) {
    int row = blockIdx.x;
    int t   = threadIdx.x;          // 128 threads
    const float* xr = x + (size_t)row * DIM;

    float v[4];
#pragma unroll
    for (int i = 0; i < 4; i++) v[i] = xr[t + 128 * i];

    float ss = 0.f, mx = -dev_inf();
#pragma unroll
    for (int i = 0; i < 4; i++) { ss += v[i] * v[i]; mx = fmaxf(mx, v[i]); }
#pragma unroll
    for (int o = 16; o; o >>= 1) {
        ss += __shfl_xor_sync(0xffffffffu, ss, o);
        mx  = fmaxf(mx, __shfl_xor_sync(0xffffffffu, mx, o));
    }
    __shared__ float s_ss[4], s_mx[4], s_sq[4], s_se[4];
    int w = t >> 5, l = t & 31;
    if (l == 0) { s_ss[w] = ss; s_mx[w] = mx; }
    __syncthreads();
    ss = s_ss[0] + s_ss[1] + s_ss[2] + s_ss[3];
    mx = fmaxf(fmaxf(s_mx[0], s_mx[1]), fmaxf(s_mx[2], s_mx[3]));

    float norm = sqrtf(ss);
    float sq = 0.f, se = 0.f;
#pragma unroll
    for (int i = 0; i < 4; i++) {
        float xn = v[i] / norm;
        sq += xn * xn;
        se += expf(v[i] - mx);
    }
#pragma unroll
    for (int o = 16; o; o >>= 1) {
        sq += __shfl_xor_sync(0xffffffffu, sq, o);
        se += __shfl_xor_sync(0xffffffffu, se, o);
    }
    if (l == 0) { s_sq[w] = sq; s_se[w] = se; }
    __syncthreads();

    if (t == 0) {
        float sqt = s_sq[0] + s_sq[1] + s_sq[2] + s_sq[3];
        float set = s_se[0] + s_se[1] + s_se[2] + s_se[3];
        int lb = g_lab64 ? (int)((const long long*)labraw)[row]
                         : ((const int*)labraw)[row];
        g_sq[row]  = sqt;
        g_ce[row]  = mx + logf(set) - xr[lb];
        g_lab[row] = lb;
        g_pos[row] = f2ord(-dev_inf());
        g_neg[row] = f2ord(dev_inf());
    }

#pragma unroll
    for (int i = 0; i < 4; i++) {
        size_t idx = (size_t)row * DIM + t + 128 * i;
        __nv_bfloat16 h = __float2bfloat16(v[i]);
        g_hi[idx] = h;
        g_lo[idx] = __float2bfloat16(v[i] - __bfloat162float(h));
    }
}

// ---------------- mma helpers ----------------------------------------------
__device__ __forceinline__ void ldm_x4(uint32_t* d, uint32_t addr) {
    asm volatile("ldmatrix.sync.aligned.m8n8.x4.shared.b16 {%0,%1,%2,%3}, [%4];\n"
                 : "=r"(d[0]), "=r"(d[1]), "=r"(d[2]), "=r"(d[3]) : "r"(addr));
}
__device__ __forceinline__ void mma16816(float* c, const uint32_t* a, const uint32_t* b) {
    asm volatile(
        "mma.sync.aligned.m16n8k16.row.col.f32.bf16.bf16.f32 "
        "{%0,%1,%2,%3}, {%4,%5,%6,%7}, {%8,%9}, {%0,%1,%2,%3};\n"
        : "+f"(c[0]), "+f"(c[1]), "+f"(c[2]), "+f"(c[3])
        : "r"(a[0]), "r"(a[1]), "r"(a[2]), "r"(a[3]), "r"(b[0]), "r"(b[1]));
}
__device__ __forceinline__ void cpasync16(uint32_t dst, const void* src) {
    asm volatile("cp.async.cg.shared.global [%0], [%1], 16;" :: "r"(dst), "l"(src));
}

// swizzled 16B-chunk index for (row r, logical chunk c) inside a 128x32 bf16 tile
__device__ __forceinline__ int swz(int r, int c) { return r * 4 + (c ^ ((r >> 1) & 3)); }

// ---------------- fused triangular GEMM + masked max/min epilogue ----------
__global__ void __launch_bounds__(256) gemm_kernel() {
    extern __shared__ __align__(1024) char smdyn[];
    // map linear block -> upper-triangular tile (bi <= bj)
    int b = blockIdx.x;
    int bi = 0;
    while ((bi + 1) * BT - ((bi + 1) * bi) / 2 <= b) bi++;
    int bj = bi + (b - (bi * BT - (bi * (bi - 1)) / 2));

    const int tid  = threadIdx.x;
    const int lane = tid & 31, warp = tid >> 5;
    const int wm = warp & 3, wn = warp >> 2;   // 4 x 2 warp grid: 32-row x 64-col per warp

    __shared__ float s_sqi[128], s_sqj[128];
    __shared__ int   s_li[128], s_lj[128];

    const int rowi0 = bi * 128, rowj0 = bj * 128;
    if (tid < 128) { s_sqi[tid] = g_sq[rowi0 + tid]; s_li[tid] = g_lab[rowi0 + tid]; }
    else { int t2 = tid - 128; s_sqj[t2] = g_sq[rowj0 + t2]; s_lj[t2] = g_lab[rowj0 + t2]; }

    float acc[2][8][4];
#pragma unroll
    for (int mi = 0; mi < 2; mi++)
#pragma unroll
        for (int ni = 0; ni < 8; ni++)
#pragma unroll
            for (int k = 0; k < 4; k++) acc[mi][ni][k] = 0.f;

    uint32_t smem0;
    asm("{ .reg .u64 t; cvta.to.shared.u64 t, %1; cvt.u32.u64 %0, t; }"
        : "=r"(smem0) : "l"(smdyn));

    // precomputed per-thread load geometry (two 16B chunks per tile per k-chunk)
    const int r0 = tid >> 2,        c0 = tid & 3;
    const int r1 = (tid + 256) >> 2, c1 = (tid + 256) & 3;
    const uint32_t so0 = (uint32_t)swz(r0, c0) << 4;
    const uint32_t so1 = (uint32_t)swz(r1, c1) << 4;

    auto issue_chunk = [&](int k, int stage) {
        const int kt = k * KC;
        const uint32_t sb = smem0 + stage * STAGEB;
        size_t a0 = (size_t)(rowi0 + r0) * DIM + kt + c0 * 8;
        size_t a1 = (size_t)(rowi0 + r1) * DIM + kt + c1 * 8;
        size_t b0 = (size_t)(rowj0 + r0) * DIM + kt + c0 * 8;
        size_t b1 = (size_t)(rowj0 + r1) * DIM + kt + c1 * 8;
        cpasync16(sb +         so0, g_hi + a0);
        cpasync16(sb +         so1, g_hi + a1);
        cpasync16(sb +  8192 + so0, g_lo + a0);
        cpasync16(sb +  8192 + so1, g_lo + a1);
        cpasync16(sb + 16384 + so0, g_hi + b0);
        cpasync16(sb + 16384 + so1, g_hi + b1);
        cpasync16(sb + 24576 + so0, g_lo + b0);
        cpasync16(sb + 24576 + so1, g_lo + b1);
        asm volatile("cp.async.commit_group;" ::: "memory");
    };

    issue_chunk(0, 0);

    const int m4 = lane >> 3, ri = lane & 7;

    for (int k = 0; k < NCH; k++) {
        if (k + 1 < NCH) issue_chunk(k + 1, (k + 1) & 1);
        if (k + 1 < NCH) asm volatile("cp.async.wait_group 1;" ::: "memory");
        else             asm volatile("cp.async.wait_group 0;" ::: "memory");
        __syncthreads();

        const uint32_t sb = smem0 + (k & 1) * STAGEB;
        const uint32_t baseAh = sb, baseAl = sb + 8192;
        const uint32_t baseBh = sb + 16384, baseBl = sb + 24576;

#pragma unroll
        for (int kk = 0; kk < 2; kk++) {
            uint32_t ah[2][4], al[2][4];
#pragma unroll
            for (int mi = 0; mi < 2; mi++) {
                int r = wm * 32 + mi * 16 + (m4 & 1) * 8 + ri;
                int c = kk * 2 + (m4 >> 1);
                uint32_t off = (uint32_t)swz(r, c) << 4;
                ldm_x4(ah[mi], baseAh + off);
                ldm_x4(al[mi], baseAl + off);
            }
            uint32_t bh[4][4], bl[4][4];
#pragma unroll
            for (int p4 = 0; p4 < 4; p4++) {
                int r = wn * 64 + p4 * 16 + (m4 >> 1) * 8 + ri;
                int c = kk * 2 + (m4 & 1);
                uint32_t off = (uint32_t)swz(r, c) << 4;
                ldm_x4(bh[p4], baseBh + off);
                ldm_x4(bl[p4], baseBl + off);
            }
#pragma unroll
            for (int mi = 0; mi < 2; mi++)
#pragma unroll
                for (int ni = 0; ni < 8; ni++) {
                    const uint32_t* fh = &bh[ni >> 1][(ni & 1) * 2];
                    const uint32_t* fl = &bl[ni >> 1][(ni & 1) * 2];
                    mma16816(acc[mi][ni], ah[mi], fh);   // hi*hi
                    mma16816(acc[mi][ni], ah[mi], fl);   // hi*lo
                    mma16816(acc[mi][ni], al[mi], fh);   // lo*hi
                }
        }
        __syncthreads();
    }

    // ---------------- epilogue: dist + masked max/min reductions -----------
    const int g = lane >> 2, tg = lane & 3;
    const float NEG = -dev_inf(), POS = dev_inf();
    float rmax[2][2], rmin[2][2];
#pragma unroll
    for (int mi = 0; mi < 2; mi++)
#pragma unroll
        for (int h = 0; h < 2; h++) { rmax[mi][h] = NEG; rmin[mi][h] = POS; }
    float cmx[16], cmn[16];
#pragma unroll
    for (int s = 0; s < 16; s++) { cmx[s] = NEG; cmn[s] = POS; }

#pragma unroll
    for (int mi = 0; mi < 2; mi++)
#pragma unroll
        for (int h = 0; h < 2; h++) {
            int li = wm * 32 + mi * 16 + h * 8 + g;
            int labi = s_li[li];
            float sqi = s_sqi[li];
#pragma unroll
            for (int ni = 0; ni < 8; ni++)
#pragma unroll
                for (int cc = 0; cc < 2; cc++) {
                    int lj = wn * 64 + ni * 8 + tg * 2 + cc;
                    float d = sqi + s_sqj[lj] - 2.0f * acc[mi][ni][h * 2 + cc];
                    int s = ni * 2 + cc;
                    if (labi == s_lj[lj]) {
                        rmax[mi][h] = fmaxf(rmax[mi][h], d);
                        cmx[s] = fmaxf(cmx[s], d);
                    } else {
                        rmin[mi][h] = fminf(rmin[mi][h], d);
                        cmn[s] = fminf(cmn[s], d);
                    }
                }
        }

    // row reduction: lanes sharing g differ in tg (low 2 bits)
#pragma unroll
    for (int mi = 0; mi < 2; mi++)
#pragma unroll
        for (int h = 0; h < 2; h++) {
            float m_ = rmax[mi][h], n_ = rmin[mi][h];
            m_ = fmaxf(m_, __shfl_xor_sync(0xffffffffu, m_, 1));
            m_ = fmaxf(m_, __shfl_xor_sync(0xffffffffu, m_, 2));
            n_ = fminf(n_, __shfl_xor_sync(0xffffffffu, n_, 1));
            n_ = fminf(n_, __shfl_xor_sync(0xffffffffu, n_, 2));
            if (tg == 0) {
                int grow = rowi0 + wm * 32 + mi * 16 + h * 8 + g;
                atomicMax(&g_pos[grow], f2ord(m_));
                atomicMin(&g_neg[grow], f2ord(n_));
            }
        }

    // column reduction (symmetry): lanes sharing tg differ in g (bits 2..4)
    if (bi != bj) {
#pragma unroll
        for (int s = 0; s < 16; s++) {
            float m_ = cmx[s], n_ = cmn[s];
            m_ = fmaxf(m_, __shfl_xor_sync(0xffffffffu, m_, 4));
            m_ = fmaxf(m_, __shfl_xor_sync(0xffffffffu, m_, 8));
            m_ = fmaxf(m_, __shfl_xor_sync(0xffffffffu, m_, 16));
            n_ = fminf(n_, __shfl_xor_sync(0xffffffffu, n_, 4));
            n_ = fminf(n_, __shfl_xor_sync(0xffffffffu, n_, 8));
            n_ = fminf(n_, __shfl_xor_sync(0xffffffffu, n_, 16));
            if (g == 0) {
                int gcol = rowj0 + wn * 64 + (s >> 1) * 8 + tg * 2 + (s & 1);
                atomicMax(&g_pos[gcol], f2ord(m_));
                atomicMin(&g_neg[gcol], f2ord(n_));
            }
        }
    }
}

// ---------------- finalize: deterministic tree reduction --------------------
__global__ void finalize_kernel(float* out) {
    __shared__ float sh[1024];
    int t = threadIdx.x;
    float ts = 0.f, cs = 0.f;
    for (int i = t; i < N_ROWS; i += 1024) {
        ts += fmaxf(ord2f(g_pos[i]) - ord2f(g_neg[i]) + MARGIN, 0.0f);
        cs += g_ce[i];
    }
    sh[t] = ts; __syncthreads();
    for (int o = 512; o; o >>= 1) { if (t < o) sh[t] += sh[t + o]; __syncthreads(); }
    float tt = sh[0]; __syncthreads();
    sh[t] = cs; __syncthreads();
    for (int o = 512; o; o >>= 1) { if (t < o) sh[t] += sh[t + o]; __syncthreads(); }
    if (t == 0) out[0] = tt / (float)N_ROWS + sh[0] / (float)N_ROWS;
}

// ---------------- entry -----------------------------------------------------
extern "C" void kernel_launch(void* const* d_in, const int* in_sizes, int n_in,
                              void* d_out, int out_size) {
    const float* x   = (const float*)d_in[0];
    const void*  lab = d_in[1];

    cudaFuncSetAttribute(gemm_kernel, cudaFuncAttributeMaxDynamicSharedMemorySize, SMEMDYN);
    detect_kernel<<<1, 256>>>((const int*)lab);
    prep_kernel<<<N_ROWS, 128>>>(x, lab);
    gemm_kernel<<<(BT * (BT + 1)) / 2, 256, SMEMDYN>>>();
    finalize_kernel<<<1, 1024>>>((float*)d_out);
}

// round 4
// speedup vs baseline: 3.2899x; 2.2521x over previous
#include <cuda_runtime.h>
#include <cuda_fp16.h>
#include <cstdint>

#define N_ROWS 8192
#define DIM    512
#define BT     64            // 8192/128 tiles per dimension
#define MARGIN 0.35f
#define KC     64            // K elems per smem chunk (128B rows)
#define NCH    (DIM / KC)    // 8
#define TILEB  (128 * KC * 2)       // 16384 per operand tile
#define STAGEB (2 * TILEB)          // A + B
#define SMEMDYN (2 * STAGEB)        // double buffer = 65536
#define NTILES ((BT * (BT + 1)) / 2)

// ---------------- scratch (device globals; no allocation allowed) ----------
__device__ __align__(16) __half g_h[N_ROWS * DIM];
__device__ float    g_sq[N_ROWS];
__device__ float    g_ce[N_ROWS];
__device__ unsigned g_pos[N_ROWS];
__device__ unsigned g_neg[N_ROWS];
__device__ int      g_lab[N_ROWS];
__device__ int      g_lab64;
__device__ unsigned g_done;

// ---------------- float <-> monotone unsigned encoding ---------------------
__device__ __forceinline__ unsigned f2ord(float f) {
    unsigned u = __float_as_uint(f);
    return (u & 0x80000000u) ? ~u : (u | 0x80000000u);
}
__device__ __forceinline__ float ord2f(unsigned u) {
    unsigned b = (u & 0x80000000u) ? (u ^ 0x80000000u) : ~u;
    return __uint_as_float(b);
}
__device__ __forceinline__ float dev_inf() { return __int_as_float(0x7f800000); }

// ---------------- label width autodetect + counter reset --------------------
__global__ void detect_kernel(const int* raw) {
    __shared__ int bad;
    if (threadIdx.x == 0) { bad = 0; g_done = 0; }
    __syncthreads();
    for (int i = threadIdx.x; i < 2048; i += blockDim.x)
        if (raw[2 * i + 1] != 0) bad = 1;
    __syncthreads();
    if (threadIdx.x == 0) g_lab64 = bad ? 0 : 1;
}

// ---------------- prep: norms, CE, fp16 cast, init reductions ---------------
__global__ void prep_kernel(const float* __restrict__ x, const void* __restrict__ labraw) {
    int row = blockIdx.x;
    int t   = threadIdx.x;          // 128 threads
    const float* xr = x + (size_t)row * DIM;

    float v[4];
#pragma unroll
    for (int i = 0; i < 4; i++) v[i] = xr[t + 128 * i];

    float ss = 0.f, mx = -dev_inf();
#pragma unroll
    for (int i = 0; i < 4; i++) { ss += v[i] * v[i]; mx = fmaxf(mx, v[i]); }
#pragma unroll
    for (int o = 16; o; o >>= 1) {
        ss += __shfl_xor_sync(0xffffffffu, ss, o);
        mx  = fmaxf(mx, __shfl_xor_sync(0xffffffffu, mx, o));
    }
    __shared__ float s_ss[4], s_mx[4], s_sq[4], s_se[4];
    int w = t >> 5, l = t & 31;
    if (l == 0) { s_ss[w] = ss; s_mx[w] = mx; }
    __syncthreads();
    ss = s_ss[0] + s_ss[1] + s_ss[2] + s_ss[3];
    mx = fmaxf(fmaxf(s_mx[0], s_mx[1]), fmaxf(s_mx[2], s_mx[3]));

    float norm = sqrtf(ss);
    float sq = 0.f, se = 0.f;
#pragma unroll
    for (int i = 0; i < 4; i++) {
        float xn = v[i] / norm;
        sq += xn * xn;
        se += expf(v[i] - mx);
    }
#pragma unroll
    for (int o = 16; o; o >>= 1) {
        sq += __shfl_xor_sync(0xffffffffu, sq, o);
        se += __shfl_xor_sync(0xffffffffu, se, o);
    }
    if (l == 0) { s_sq[w] = sq; s_se[w] = se; }
    __syncthreads();

    if (t == 0) {
        float sqt = s_sq[0] + s_sq[1] + s_sq[2] + s_sq[3];
        float set = s_se[0] + s_se[1] + s_se[2] + s_se[3];
        int lb = g_lab64 ? (int)((const long long*)labraw)[row]
                         : ((const int*)labraw)[row];
        g_sq[row]  = sqt;
        g_ce[row]  = mx + logf(set) - xr[lb];
        g_lab[row] = lb;
        g_pos[row] = f2ord(-dev_inf());
        g_neg[row] = f2ord(dev_inf());
    }

#pragma unroll
    for (int i = 0; i < 4; i++)
        g_h[(size_t)row * DIM + t + 128 * i] = __float2half_rn(v[i]);
}

// ---------------- mma helpers ----------------------------------------------
__device__ __forceinline__ void ldm_x4(uint32_t* d, uint32_t addr) {
    asm volatile("ldmatrix.sync.aligned.m8n8.x4.shared.b16 {%0,%1,%2,%3}, [%4];\n"
                 : "=r"(d[0]), "=r"(d[1]), "=r"(d[2]), "=r"(d[3]) : "r"(addr));
}
__device__ __forceinline__ void mma16816(float* c, const uint32_t* a, const uint32_t* b) {
    asm volatile(
        "mma.sync.aligned.m16n8k16.row.col.f32.f16.f16.f32 "
        "{%0,%1,%2,%3}, {%4,%5,%6,%7}, {%8,%9}, {%0,%1,%2,%3};\n"
        : "+f"(c[0]), "+f"(c[1]), "+f"(c[2]), "+f"(c[3])
        : "r"(a[0]), "r"(a[1]), "r"(a[2]), "r"(a[3]), "r"(b[0]), "r"(b[1]));
}
__device__ __forceinline__ void cpasync16(uint32_t dst, const void* src) {
    asm volatile("cp.async.cg.shared.global [%0], [%1], 16;" :: "r"(dst), "l"(src));
}

// swizzled 16B-chunk byte offset for (row r, logical chunk c) in 128x64 fp16 tile
__device__ __forceinline__ uint32_t swz8(int r, int c) {
    return (uint32_t)((r * 8 + (c ^ (r & 7))) << 4);
}

// ---------------- fused triangular GEMM + masked max/min + finalize --------
__global__ void __launch_bounds__(256, 2) gemm_kernel(float* out) {
    extern __shared__ __align__(1024) char smdyn[];
    // map linear block -> upper-triangular tile (bi <= bj)
    int b = blockIdx.x;
    int bi = 0;
    while ((bi + 1) * BT - ((bi + 1) * bi) / 2 <= b) bi++;
    int bj = bi + (b - (bi * BT - (bi * (bi - 1)) / 2));

    const int tid  = threadIdx.x;
    const int lane = tid & 31, warp = tid >> 5;
    const int wm = warp & 3, wn = warp >> 2;   // 4x2 warp grid: 32-row x 64-col per warp

    __shared__ float s_sqi[128], s_sqj[128];
    __shared__ int   s_li[128], s_lj[128];

    const int rowi0 = bi * 128, rowj0 = bj * 128;
    if (tid < 128) { s_sqi[tid] = g_sq[rowi0 + tid]; s_li[tid] = g_lab[rowi0 + tid]; }
    else { int t2 = tid - 128; s_sqj[t2] = g_sq[rowj0 + t2]; s_lj[t2] = g_lab[rowj0 + t2]; }

    float acc[2][8][4];
#pragma unroll
    for (int mi = 0; mi < 2; mi++)
#pragma unroll
        for (int ni = 0; ni < 8; ni++)
#pragma unroll
            for (int k = 0; k < 4; k++) acc[mi][ni][k] = 0.f;

    uint32_t smem0;
    asm("{ .reg .u64 t; cvta.to.shared.u64 t, %1; cvt.u32.u64 %0, t; }"
        : "=r"(smem0) : "l"(smdyn));

    auto issue_chunk = [&](int k, int stage) {
        const int kt = k * KC;
        const uint32_t sbA = smem0 + stage * STAGEB;
        const uint32_t sbB = sbA + TILEB;
#pragma unroll
        for (int rep = 0; rep < 4; rep++) {
            int q = rep * 256 + tid;            // 0..1023
            int r = q >> 3, c = q & 7;
            uint32_t so = swz8(r, c);
            size_t ga = (size_t)(rowi0 + r) * DIM + kt + c * 8;
            size_t gb = (size_t)(rowj0 + r) * DIM + kt + c * 8;
            cpasync16(sbA + so, g_h + ga);
            cpasync16(sbB + so, g_h + gb);
        }
        asm volatile("cp.async.commit_group;" ::: "memory");
    };

    issue_chunk(0, 0);

    const int m4 = lane >> 3, ri = lane & 7;

    for (int k = 0; k < NCH; k++) {
        if (k + 1 < NCH) {
            issue_chunk(k + 1, (k + 1) & 1);
            asm volatile("cp.async.wait_group 1;" ::: "memory");
        } else {
            asm volatile("cp.async.wait_group 0;" ::: "memory");
        }
        __syncthreads();

        const uint32_t baseA = smem0 + (k & 1) * STAGEB;
        const uint32_t baseB = baseA + TILEB;

#pragma unroll
        for (int kk = 0; kk < 4; kk++) {
            uint32_t ah[2][4];
#pragma unroll
            for (int mi = 0; mi < 2; mi++) {
                int r = wm * 32 + mi * 16 + (m4 & 1) * 8 + ri;
                int c = kk * 2 + (m4 >> 1);
                ldm_x4(ah[mi], baseA + swz8(r, c));
            }
            uint32_t bh[4][4];
#pragma unroll
            for (int p4 = 0; p4 < 4; p4++) {
                int r = wn * 64 + p4 * 16 + (m4 >> 1) * 8 + ri;
                int c = kk * 2 + (m4 & 1);
                ldm_x4(bh[p4], baseB + swz8(r, c));
            }
#pragma unroll
            for (int mi = 0; mi < 2; mi++)
#pragma unroll
                for (int ni = 0; ni < 8; ni++)
                    mma16816(acc[mi][ni], ah[mi], &bh[ni >> 1][(ni & 1) * 2]);
        }
        __syncthreads();
    }

    // ---------------- epilogue: dist + masked max/min reductions -----------
    const int g = lane >> 2, tg = lane & 3;
    const float NEG = -dev_inf(), POS = dev_inf();
    float rmax[2][2], rmin[2][2];
#pragma unroll
    for (int mi = 0; mi < 2; mi++)
#pragma unroll
        for (int h = 0; h < 2; h++) { rmax[mi][h] = NEG; rmin[mi][h] = POS; }
    float cmx[16], cmn[16];
#pragma unroll
    for (int s = 0; s < 16; s++) { cmx[s] = NEG; cmn[s] = POS; }

#pragma unroll
    for (int mi = 0; mi < 2; mi++)
#pragma unroll
        for (int h = 0; h < 2; h++) {
            int li = wm * 32 + mi * 16 + h * 8 + g;
            int labi = s_li[li];
            float sqi = s_sqi[li];
#pragma unroll
            for (int ni = 0; ni < 8; ni++)
#pragma unroll
                for (int cc = 0; cc < 2; cc++) {
                    int lj = wn * 64 + ni * 8 + tg * 2 + cc;
                    float d = sqi + s_sqj[lj] - 2.0f * acc[mi][ni][h * 2 + cc];
                    int s = ni * 2 + cc;
                    if (labi == s_lj[lj]) {
                        rmax[mi][h] = fmaxf(rmax[mi][h], d);
                        cmx[s] = fmaxf(cmx[s], d);
                    } else {
                        rmin[mi][h] = fminf(rmin[mi][h], d);
                        cmn[s] = fminf(cmn[s], d);
                    }
                }
        }

    // row reduction: lanes sharing g differ in tg (low 2 bits)
#pragma unroll
    for (int mi = 0; mi < 2; mi++)
#pragma unroll
        for (int h = 0; h < 2; h++) {
            float m_ = rmax[mi][h], n_ = rmin[mi][h];
            m_ = fmaxf(m_, __shfl_xor_sync(0xffffffffu, m_, 1));
            m_ = fmaxf(m_, __shfl_xor_sync(0xffffffffu, m_, 2));
            n_ = fminf(n_, __shfl_xor_sync(0xffffffffu, n_, 1));
            n_ = fminf(n_, __shfl_xor_sync(0xffffffffu, n_, 2));
            if (tg == 0) {
                int grow = rowi0 + wm * 32 + mi * 16 + h * 8 + g;
                atomicMax(&g_pos[grow], f2ord(m_));
                atomicMin(&g_neg[grow], f2ord(n_));
            }
        }

    // column reduction (symmetry): lanes sharing tg differ in g (bits 2..4)
    if (bi != bj) {
#pragma unroll
        for (int s = 0; s < 16; s++) {
            float m_ = cmx[s], n_ = cmn[s];
            m_ = fmaxf(m_, __shfl_xor_sync(0xffffffffu, m_, 4));
            m_ = fmaxf(m_, __shfl_xor_sync(0xffffffffu, m_, 8));
            m_ = fmaxf(m_, __shfl_xor_sync(0xffffffffu, m_, 16));
            n_ = fminf(n_, __shfl_xor_sync(0xffffffffu, n_, 4));
            n_ = fminf(n_, __shfl_xor_sync(0xffffffffu, n_, 8));
            n_ = fminf(n_, __shfl_xor_sync(0xffffffffu, n_, 16));
            if (g == 0) {
                int gcol = rowj0 + wn * 64 + (s >> 1) * 8 + tg * 2 + (s & 1);
                atomicMax(&g_pos[gcol], f2ord(m_));
                atomicMin(&g_neg[gcol], f2ord(n_));
            }
        }
    }

    // ---------------- last-block finalize (deterministic tree) -------------
    __shared__ unsigned s_last;
    __syncthreads();
    if (tid == 0) {
        __threadfence();
        s_last = (atomicAdd(&g_done, 1u) == (unsigned)(NTILES - 1));
    }
    __syncthreads();
    if (s_last) {
        __shared__ float sh[256];
        float ts = 0.f, cs = 0.f;
        for (int i = tid; i < N_ROWS; i += 256) {
            float p = ord2f(__ldcg(&g_pos[i]));
            float n = ord2f(__ldcg(&g_neg[i]));
            ts += fmaxf(p - n + MARGIN, 0.0f);
            cs += __ldcg(&g_ce[i]);
        }
        sh[tid] = ts; __syncthreads();
        for (int o = 128; o; o >>= 1) { if (tid < o) sh[tid] += sh[tid + o]; __syncthreads(); }
        float tt = sh[0]; __syncthreads();
        sh[tid] = cs; __syncthreads();
        for (int o = 128; o; o >>= 1) { if (tid < o) sh[tid] += sh[tid + o]; __syncthreads(); }
        if (tid == 0) out[0] = tt / (float)N_ROWS + sh[0] / (float)N_ROWS;
    }
}

// ---------------- entry -----------------------------------------------------
extern "C" void kernel_launch(void* const* d_in, const int* in_sizes, int n_in,
                              void* d_out, int out_size) {
    const float* x   = (const float*)d_in[0];
    const void*  lab = d_in[1];

    cudaFuncSetAttribute(gemm_kernel, cudaFuncAttributeMaxDynamicSharedMemorySize, SMEMDYN);
    detect_kernel<<<1, 256>>>((const int*)lab);
    prep_kernel<<<N_ROWS, 128>>>(x, lab);
    gemm_kernel<<<NTILES, 256, SMEMDYN>>>((float*)d_out);
}